// round 4
// baseline (speedup 1.0000x reference)
#include <cuda_runtime.h>
#include <math.h>

#define D 64
#define S 8
#define EPB 4
#define NTHREADS 256

// softmax over 8 values read from shared (broadcast); result in local regs
__device__ __forceinline__ void softmax8(const float* __restrict__ raw, float* w) {
    float m = raw[0];
#pragma unroll
    for (int s = 1; s < S; s++) m = fmaxf(m, raw[s]);
    float sum = 0.f;
#pragma unroll
    for (int s = 0; s < S; s++) { w[s] = expf(raw[s] - m); sum += w[s]; }
    float inv = 1.0f / sum;
#pragma unroll
    for (int s = 0; s < S; s++) w[s] *= inv;
}

__device__ __forceinline__ float warp_sum(float p) {
    p += __shfl_down_sync(0xffffffffu, p, 16);
    p += __shfl_down_sync(0xffffffffu, p, 8);
    p += __shfl_down_sync(0xffffffffu, p, 4);
    p += __shfl_down_sync(0xffffffffu, p, 2);
    p += __shfl_down_sync(0xffffffffu, p, 1);
    return p;
}

__global__ __launch_bounds__(NTHREADS)
void sestkgcn_kernel(
    const int* __restrict__ U, const int* __restrict__ V,
    const float* __restrict__ usr_feat, const float* __restrict__ item_feat,
    const float* __restrict__ rel_feat,
    const int* __restrict__ n_uu, const float* __restrict__ uu_st,
    const int* __restrict__ n_ui, const float* __restrict__ ui_rat,
    const float* __restrict__ ui_vot, const float* __restrict__ ui_tim,
    const int* __restrict__ n_iu, const float* __restrict__ iu_rat,
    const float* __restrict__ iu_vot, const float* __restrict__ iu_tim,
    const int* __restrict__ n_ii, const int* __restrict__ n_ir,
    const float* __restrict__ Wu, const float* __restrict__ bu,
    const float* __restrict__ Wv, const float* __restrict__ bv,
    float* __restrict__ out, int batch)
{
    __shared__ __align__(16) float sWu[D * D];
    __shared__ __align__(16) float sWv[D * D];
    __shared__ float sbu[D], sbv[D];
    __shared__ __align__(16) float sxu[D][EPB]; // transposed: [k][elem] for float4 broadcast
    __shared__ __align__(16) float sxv[D][EPB];
    __shared__ float suh[EPB][D];
    __shared__ float svh[EPB][D];
    __shared__ int   snid[EPB][4][S];  // neighbor indices: uu, ui, iu, ii
    __shared__ float swraw[EPB][3][S]; // raw attention scores: uu, ui, iu
    __shared__ int   srid[EPB][S];     // relation indices
    __shared__ float sattp[EPB][S][2]; // attention partials (2 warps per group)
    __shared__ float sred[EPB][2];     // final dot partials

    const int tid = threadIdx.x;

    // preload transforms (once per block; amortized over grid-stride loop)
    for (int i = tid; i < D * D; i += NTHREADS) { sWu[i] = Wu[i]; sWv[i] = Wv[i]; }
    if (tid < D) { sbu[tid] = bu[tid]; sbv[tid] = bv[tid]; }

    const int g    = tid >> 6;   // element-in-block (0..3)
    const int t    = tid & 63;   // dim lane (0..63)
    const int wgrp = t >> 5;     // warp within group (0/1)
    const int lane = t & 31;
    const int ngroups = (batch + EPB - 1) / EPB;

    for (int eg = blockIdx.x; eg < ngroups; eg += gridDim.x) {
        const int e = eg * EPB + g;
        const bool valid = (e < batch);
        const int ec = valid ? e : (batch - 1);

        const int u = U[ec];
        const int v = V[ec];

        const float ue = usr_feat[u * D + t];
        const float ve = item_feat[v * D + t];

        // first warp of each group loads all neighbor indices / raw scores
        if (t < 32) {
            const int set = t >> 3, s = t & 7;
            if (set == 0) {
                snid[g][0][s]  = n_uu[u * S + s];
                swraw[g][0][s] = uu_st[u * S + s];
            } else if (set == 1) {
                snid[g][1][s]  = n_ui[u * S + s];
                swraw[g][1][s] = ui_rat[u * S + s] * ui_vot[u * S + s] * ui_tim[u * S + s];
            } else if (set == 2) {
                snid[g][2][s]  = n_iu[v * S + s];
                swraw[g][2][s] = iu_rat[v * S + s] * iu_vot[v * S + s] * iu_tim[v * S + s];
            } else {
                snid[g][3][s] = n_ii[v * S + s];
                srid[g][s]    = n_ir[v * S + s];
            }
        }
        __syncthreads();  // #1: indices/scores ready

        float w[S];

        // ---- user side: social neighbor aggregation ----
        softmax8(&swraw[g][0][0], w);
        float agg = 0.f;
#pragma unroll
        for (int s = 0; s < S; s++) agg = fmaf(w[s], usr_feat[snid[g][0][s] * D + t], agg);
        float xu = ue + agg;

        // ---- user side: interacted-item aggregation ----
        softmax8(&swraw[g][1][0], w);
        agg = 0.f;
#pragma unroll
        for (int s = 0; s < S; s++) agg = fmaf(w[s], item_feat[snid[g][1][s] * D + t], agg);
        xu += agg;
        sxu[t][g] = xu;

        // ---- item side: interacting-user aggregation (kept in reg) ----
        softmax8(&swraw[g][2][0], w);
        float aggiu = 0.f;
#pragma unroll
        for (int s = 0; s < S; s++) aggiu = fmaf(w[s], usr_feat[snid[g][2][s] * D + t], aggiu);

        // ---- KG attention: att[s] = dot(u_emb, rel_s) across 64 dims ----
        float part[S];
#pragma unroll
        for (int s = 0; s < S; s++) part[s] = ue * rel_feat[srid[g][s] * D + t];
#pragma unroll
        for (int s = 0; s < S; s++) {
            float p = warp_sum(part[s]);
            if (lane == 0) sattp[g][s][wgrp] = p;
        }
        __syncthreads();  // #2: attention partials + sxu ready

        float att[S];
#pragma unroll
        for (int s = 0; s < S; s++) att[s] = sattp[g][s][0] + sattp[g][s][1];
        softmax8(att, w);
        agg = 0.f;
#pragma unroll
        for (int s = 0; s < S; s++) agg = fmaf(w[s], item_feat[snid[g][3][s] * D + t], agg);
        sxv[t][g] = ve + aggiu + agg;
        __syncthreads();  // #3: sxv ready

        // ---- matvec phase: 64 threads user, 64 threads item, W read once for 4 elems ----
        if (tid < 128) {
            const int c = tid & 63;
            const bool isU = (tid < 64);
            const float* __restrict__ Ws = isU ? sWu : sWv;
            const float (*__restrict__ xs)[EPB] = isU ? sxu : sxv;
            const float bb = isU ? sbu[c] : sbv[c];
            float a0 = bb, a1 = bb, a2 = bb, a3 = bb;
#pragma unroll 16
            for (int k = 0; k < D; k++) {
                const float wv = Ws[k * D + c];
                const float4 xq = *reinterpret_cast<const float4*>(&xs[k][0]);
                a0 = fmaf(xq.x, wv, a0);
                a1 = fmaf(xq.y, wv, a1);
                a2 = fmaf(xq.z, wv, a2);
                a3 = fmaf(xq.w, wv, a3);
            }
            float (*__restrict__ hdst)[D] = isU ? suh : svh;
            hdst[0][c] = fmaxf(a0, 0.f);
            hdst[1][c] = fmaxf(a1, 0.f);
            hdst[2][c] = fmaxf(a2, 0.f);
            hdst[3][c] = fmaxf(a3, 0.f);
        }
        __syncthreads();  // #4: hidden states ready

        // ---- final dot + sigmoid ----
        float p = warp_sum(suh[g][t] * svh[g][t]);
        if (lane == 0) sred[g][wgrp] = p;
        __syncthreads();  // #5: dot partials ready

        if (t == 0 && valid) {
            const float dsum = sred[g][0] + sred[g][1];
            out[e] = 5.0f / (1.0f + expf(-dsum));
        }
        // loop-carried shared hazards are separated by >=2 __syncthreads each; safe
    }
}

extern "C" void kernel_launch(void* const* d_in, const int* in_sizes, int n_in,
                              void* d_out, int out_size) {
    const int*   U        = (const int*)  d_in[0];
    const int*   V        = (const int*)  d_in[1];
    const float* usr_feat = (const float*)d_in[2];
    const float* item_feat= (const float*)d_in[3];
    const float* rel_feat = (const float*)d_in[4];
    const int*   n_uu     = (const int*)  d_in[5];
    const float* uu_st    = (const float*)d_in[6];
    const int*   n_ui     = (const int*)  d_in[7];
    const float* ui_rat   = (const float*)d_in[8];
    const float* ui_vot   = (const float*)d_in[9];
    const float* ui_tim   = (const float*)d_in[10];
    const int*   n_iu     = (const int*)  d_in[11];
    const float* iu_rat   = (const float*)d_in[12];
    const float* iu_vot   = (const float*)d_in[13];
    const float* iu_tim   = (const float*)d_in[14];
    const int*   n_ii     = (const int*)  d_in[15];
    const int*   n_ir     = (const int*)  d_in[16];
    const float* Wu       = (const float*)d_in[17];
    const float* bu       = (const float*)d_in[18];
    const float* Wv       = (const float*)d_in[19];
    const float* bv       = (const float*)d_in[20];
    float* out = (float*)d_out;

    const int batch = in_sizes[0];
    const int ngroups = (batch + EPB - 1) / EPB;
    int nblocks = 2048;
    if (nblocks > ngroups) nblocks = ngroups;

    sestkgcn_kernel<<<nblocks, NTHREADS>>>(
        U, V, usr_feat, item_feat, rel_feat,
        n_uu, uu_st, n_ui, ui_rat, ui_vot, ui_tim,
        n_iu, iu_rat, iu_vot, iu_tim, n_ii, n_ir,
        Wu, bu, Wv, bv, out, batch);
}

// round 5
// speedup vs baseline: 1.3115x; 1.3115x over previous
#include <cuda_runtime.h>
#include <math.h>

#define D 64
#define S 8
#define EPB 16
#define NT 256
#define XPITCH 68   // floats per x row: 64 + 4 pad (keeps 16B alignment, de-conflicts banks)

__device__ __forceinline__ float hsum16(float p) {
#pragma unroll
    for (int off = 8; off > 0; off >>= 1)
        p += __shfl_xor_sync(0xffffffffu, p, off, 16);
    return p;
}

__global__ __launch_bounds__(NT)
void sestkgcn_kernel(
    const int* __restrict__ U, const int* __restrict__ V,
    const float* __restrict__ usr_feat, const float* __restrict__ item_feat,
    const float* __restrict__ rel_feat,
    const int* __restrict__ n_uu, const float* __restrict__ uu_st,
    const int* __restrict__ n_ui, const float* __restrict__ ui_rat,
    const float* __restrict__ ui_vot, const float* __restrict__ ui_tim,
    const int* __restrict__ n_iu, const float* __restrict__ iu_rat,
    const float* __restrict__ iu_vot, const float* __restrict__ iu_tim,
    const int* __restrict__ n_ii, const int* __restrict__ n_ir,
    const float* __restrict__ Wu, const float* __restrict__ bu,
    const float* __restrict__ Wv, const float* __restrict__ bv,
    float* __restrict__ out, int batch)
{
    __shared__ __align__(16) float sWu[D * D];
    __shared__ __align__(16) float sWv[D * D];
    __shared__ __align__(16) float sbu[D], sbv[D];
    __shared__ __align__(16) float sxu[EPB * XPITCH];
    __shared__ __align__(16) float sxv[EPB * XPITCH];
    __shared__ int   snid[EPB][4][S];   // neighbor ids: uu, ui, iu, ii
    __shared__ int   srid[EPB][S];      // relation ids
    __shared__ float swt[EPB][3][S];    // precomputed softmax weights: uu, ui, iu

    const int tid = threadIdx.x;

    // ---- preload transforms (once per block, amortized by grid-stride loop) ----
#pragma unroll
    for (int i = tid; i < D * D / 4; i += NT) {
        ((float4*)sWu)[i] = ((const float4*)Wu)[i];
        ((float4*)sWv)[i] = ((const float4*)Wv)[i];
    }
    if (tid < D / 4) {
        ((float4*)sbu)[tid] = ((const float4*)bu)[tid];
        ((float4*)sbv)[tid] = ((const float4*)bv)[tid];
    }

    const int e = tid >> 4;      // element within block tile (0..15)
    const int q = tid & 15;      // dim-quad / col-group lane (0..15)
    const int ngroups = (batch + EPB - 1) / EPB;

    const float4* __restrict__ uf4 = (const float4*)usr_feat;
    const float4* __restrict__ if4 = (const float4*)item_feat;
    const float4* __restrict__ rf4 = (const float4*)rel_feat;

    for (int eg = blockIdx.x; eg < ngroups; eg += gridDim.x) {
        const int ebase = eg * EPB;

        // ================= phase 1: indices + precomputed softmax weights =================
        if (tid < 48) {
            const int pe = tid / 3, side = tid - 3 * pe;
            int Ep = ebase + pe; if (Ep > batch - 1) Ep = batch - 1;
            float raw[S];
            if (side == 0) {
                const int u = U[Ep];
#pragma unroll
                for (int s = 0; s < S; s++) raw[s] = uu_st[u * S + s];
            } else if (side == 1) {
                const int u = U[Ep];
#pragma unroll
                for (int s = 0; s < S; s++)
                    raw[s] = ui_rat[u * S + s] * ui_vot[u * S + s] * ui_tim[u * S + s];
            } else {
                const int v = V[Ep];
#pragma unroll
                for (int s = 0; s < S; s++)
                    raw[s] = iu_rat[v * S + s] * iu_vot[v * S + s] * iu_tim[v * S + s];
            }
            float m = raw[0];
#pragma unroll
            for (int s = 1; s < S; s++) m = fmaxf(m, raw[s]);
            float wv[S], sum = 0.f;
#pragma unroll
            for (int s = 0; s < S; s++) { wv[s] = __expf(raw[s] - m); sum += wv[s]; }
            const float inv = __fdividef(1.0f, sum);
#pragma unroll
            for (int s = 0; s < S; s++) swt[pe][side][s] = wv[s] * inv;
        }
        if (tid >= 96) {
            const int base = (tid - 96) * 4;    // 160 threads x 4 = 640 index loads
#pragma unroll
            for (int j = 0; j < 4; j++) {
                const int i = base + j;
                const int pe = i / 40, slot = i - 40 * pe;
                int Ep = ebase + pe; if (Ep > batch - 1) Ep = batch - 1;
                if (slot < 32) {
                    const int set = slot >> 3, s = slot & 7;
                    int idx;
                    if (set == 0)      idx = n_uu[U[Ep] * S + s];
                    else if (set == 1) idx = n_ui[U[Ep] * S + s];
                    else if (set == 2) idx = n_iu[V[Ep] * S + s];
                    else               idx = n_ii[V[Ep] * S + s];
                    snid[pe][set][s] = idx;
                } else {
                    srid[pe][slot - 32] = n_ir[V[Ep] * S + (slot - 32)];
                }
            }
        }
        __syncthreads();   // #1: weights + indices ready

        // ================= phase 2: gathers + aggregations (16 threads/elem, float4) ======
        const int E = ebase + e;
        const int Ec = (E < batch) ? E : (batch - 1);
        const int u = U[Ec], v = V[Ec];

        const float4 ue = uf4[u * (D / 4) + q];
        const float4 ve = if4[v * (D / 4) + q];

        // user side: social neighbors + interacted items
        float4 xu = ue;
#pragma unroll
        for (int s = 0; s < S; s++) {
            const float w = swt[e][0][s];
            const float4 n = uf4[snid[e][0][s] * (D / 4) + q];
            xu.x = fmaf(w, n.x, xu.x); xu.y = fmaf(w, n.y, xu.y);
            xu.z = fmaf(w, n.z, xu.z); xu.w = fmaf(w, n.w, xu.w);
        }
#pragma unroll
        for (int s = 0; s < S; s++) {
            const float w = swt[e][1][s];
            const float4 n = if4[snid[e][1][s] * (D / 4) + q];
            xu.x = fmaf(w, n.x, xu.x); xu.y = fmaf(w, n.y, xu.y);
            xu.z = fmaf(w, n.z, xu.z); xu.w = fmaf(w, n.w, xu.w);
        }
        *(float4*)&sxu[e * XPITCH + 4 * q] = xu;

        // item side: interacting users
        float4 xv = ve;
#pragma unroll
        for (int s = 0; s < S; s++) {
            const float w = swt[e][2][s];
            const float4 n = uf4[snid[e][2][s] * (D / 4) + q];
            xv.x = fmaf(w, n.x, xv.x); xv.y = fmaf(w, n.y, xv.y);
            xv.z = fmaf(w, n.z, xv.z); xv.w = fmaf(w, n.w, xv.w);
        }

        // KG attention: att[s] = dot(u_emb, rel_s)
        float att[S];
#pragma unroll
        for (int s = 0; s < S; s++) {
            const float4 r = rf4[srid[e][s] * (D / 4) + q];
            float p = ue.x * r.x;
            p = fmaf(ue.y, r.y, p); p = fmaf(ue.z, r.z, p); p = fmaf(ue.w, r.w, p);
            att[s] = p;
        }
#pragma unroll
        for (int s = 0; s < S; s++) att[s] = hsum16(att[s]);
        // softmax over att in registers (replicated across the 16 owner lanes)
        {
            float m = att[0];
#pragma unroll
            for (int s = 1; s < S; s++) m = fmaxf(m, att[s]);
            float wv[S], sum = 0.f;
#pragma unroll
            for (int s = 0; s < S; s++) { wv[s] = __expf(att[s] - m); sum += wv[s]; }
            const float inv = __fdividef(1.0f, sum);
#pragma unroll
            for (int s = 0; s < S; s++) {
                const float w = wv[s] * inv;
                const float4 n = if4[snid[e][3][s] * (D / 4) + q];
                xv.x = fmaf(w, n.x, xv.x); xv.y = fmaf(w, n.y, xv.y);
                xv.z = fmaf(w, n.z, xv.z); xv.w = fmaf(w, n.w, xv.w);
            }
        }
        *(float4*)&sxv[e * XPITCH + 4 * q] = xv;
        __syncthreads();   // #2: x vectors ready

        // ================= phase 3: dual matvec + relu + dot + sigmoid ====================
        // thread -> (elem e, cols 4q..4q+3); all 256 threads active
        float4 au = ((const float4*)sbu)[q];
        float4 av = ((const float4*)sbv)[q];
        const float* __restrict__ xru = &sxu[e * XPITCH];
        const float* __restrict__ xrv = &sxv[e * XPITCH];
#pragma unroll 16
        for (int k = 0; k < D; k++) {
            const float4 w4 = ((const float4*)sWu)[k * (D / 4) + q];
            const float xk = xru[k];
            au.x = fmaf(xk, w4.x, au.x); au.y = fmaf(xk, w4.y, au.y);
            au.z = fmaf(xk, w4.z, au.z); au.w = fmaf(xk, w4.w, au.w);
        }
#pragma unroll 16
        for (int k = 0; k < D; k++) {
            const float4 w4 = ((const float4*)sWv)[k * (D / 4) + q];
            const float xk = xrv[k];
            av.x = fmaf(xk, w4.x, av.x); av.y = fmaf(xk, w4.y, av.y);
            av.z = fmaf(xk, w4.z, av.z); av.w = fmaf(xk, w4.w, av.w);
        }
        au.x = fmaxf(au.x, 0.f); au.y = fmaxf(au.y, 0.f);
        au.z = fmaxf(au.z, 0.f); au.w = fmaxf(au.w, 0.f);
        av.x = fmaxf(av.x, 0.f); av.y = fmaxf(av.y, 0.f);
        av.z = fmaxf(av.z, 0.f); av.w = fmaxf(av.w, 0.f);

        float p = au.x * av.x;
        p = fmaf(au.y, av.y, p); p = fmaf(au.z, av.z, p); p = fmaf(au.w, av.w, p);
        p = hsum16(p);

        if (q == 0 && E < batch)
            out[E] = __fdividef(5.0f, 1.0f + __expf(-p));
        __syncthreads();   // #3: protect shared tiles before next iteration
    }
}

extern "C" void kernel_launch(void* const* d_in, const int* in_sizes, int n_in,
                              void* d_out, int out_size) {
    const int*   U        = (const int*)  d_in[0];
    const int*   V        = (const int*)  d_in[1];
    const float* usr_feat = (const float*)d_in[2];
    const float* item_feat= (const float*)d_in[3];
    const float* rel_feat = (const float*)d_in[4];
    const int*   n_uu     = (const int*)  d_in[5];
    const float* uu_st    = (const float*)d_in[6];
    const int*   n_ui     = (const int*)  d_in[7];
    const float* ui_rat   = (const float*)d_in[8];
    const float* ui_vot   = (const float*)d_in[9];
    const float* ui_tim   = (const float*)d_in[10];
    const int*   n_iu     = (const int*)  d_in[11];
    const float* iu_rat   = (const float*)d_in[12];
    const float* iu_vot   = (const float*)d_in[13];
    const float* iu_tim   = (const float*)d_in[14];
    const int*   n_ii     = (const int*)  d_in[15];
    const int*   n_ir     = (const int*)  d_in[16];
    const float* Wu       = (const float*)d_in[17];
    const float* bu       = (const float*)d_in[18];
    const float* Wv       = (const float*)d_in[19];
    const float* bv       = (const float*)d_in[20];
    float* out = (float*)d_out;

    const int batch = in_sizes[0];
    const int ngroups = (batch + EPB - 1) / EPB;
    int nblocks = 2048;
    if (nblocks > ngroups) nblocks = ngroups;

    sestkgcn_kernel<<<nblocks, NT>>>(
        U, V, usr_feat, item_feat, rel_feat,
        n_uu, uu_st, n_ui, ui_rat, ui_vot, ui_tim,
        n_iu, iu_rat, iu_vot, iu_tim, n_ii, n_ir,
        Wu, bu, Wv, bv, out, batch);
}

// round 6
// speedup vs baseline: 1.8023x; 1.3743x over previous
#include <cuda_runtime.h>
#include <math.h>

#define D 64
#define S 8
#define EPB 32
#define NT 256
#define XP 36      // transposed-x pitch (floats); also reused as h rows pitch 68

__device__ __forceinline__ float hsum8(float p) {
    p += __shfl_xor_sync(0xffffffffu, p, 4, 8);
    p += __shfl_xor_sync(0xffffffffu, p, 2, 8);
    p += __shfl_xor_sync(0xffffffffu, p, 1, 8);
    return p;
}

__device__ __forceinline__ unsigned long long pk2(float lo, float hi) {
    unsigned long long r;
    asm("mov.b64 %0, {%1, %2};" : "=l"(r) : "f"(lo), "f"(hi));
    return r;
}
__device__ __forceinline__ void upk2(float& lo, float& hi, unsigned long long v) {
    asm("mov.b64 {%0, %1}, %2;" : "=f"(lo), "=f"(hi) : "l"(v));
}
__device__ __forceinline__ void fma2(unsigned long long& a, unsigned long long x,
                                     unsigned long long w) {
    asm("fma.rn.f32x2 %0, %1, %2, %0;" : "+l"(a) : "l"(x), "l"(w));
}

__global__ __launch_bounds__(NT)
void sestkgcn_kernel(
    const int* __restrict__ U, const int* __restrict__ V,
    const float* __restrict__ usr_feat, const float* __restrict__ item_feat,
    const float* __restrict__ rel_feat,
    const int* __restrict__ n_uu, const float* __restrict__ uu_st,
    const int* __restrict__ n_ui, const float* __restrict__ ui_rat,
    const float* __restrict__ ui_vot, const float* __restrict__ ui_tim,
    const int* __restrict__ n_iu, const float* __restrict__ iu_rat,
    const float* __restrict__ iu_vot, const float* __restrict__ iu_tim,
    const int* __restrict__ n_ii, const int* __restrict__ n_ir,
    const float* __restrict__ Wu, const float* __restrict__ bu,
    const float* __restrict__ Wv, const float* __restrict__ bv,
    float* __restrict__ out, int batch)
{
    __shared__ __align__(16) float sW[D * D];          // one matrix at a time
    __shared__ __align__(16) float sbu[D], sbv[D];
    __shared__ __align__(16) float sxtu[D * XP];       // transposed xu; reused as hu[32][68]
    __shared__ __align__(16) float sxtv[D * XP];       // transposed xv; reused as hv
    __shared__ int   snid[EPB][4][S];
    __shared__ int   srid[EPB][S];
    __shared__ float swt[EPB][3][S];

    const int tid = threadIdx.x;
    const int ebase = blockIdx.x * EPB;
    const float4* __restrict__ uf4 = (const float4*)usr_feat;
    const float4* __restrict__ if4 = (const float4*)item_feat;
    const float4* __restrict__ rf4 = (const float4*)rel_feat;

    // ---- preload Wu + biases ----
#pragma unroll
    for (int i = tid; i < D * D / 4; i += NT)
        ((float4*)sW)[i] = ((const float4*)Wu)[i];
    if (tid < D / 4) {
        ((float4*)sbu)[tid] = ((const float4*)bu)[tid];
        ((float4*)sbv)[tid] = ((const float4*)bv)[tid];
    }

    // ================= phase 1: softmax weights + neighbor indices ==============
    if (tid < 96) {
        const int pe = tid / 3, side = tid - 3 * pe;
        int Ep = ebase + pe; if (Ep > batch - 1) Ep = batch - 1;
        float raw[S];
        if (side == 0) {
            const int u = U[Ep];
#pragma unroll
            for (int s = 0; s < S; s++) raw[s] = uu_st[u * S + s];
        } else if (side == 1) {
            const int u = U[Ep];
#pragma unroll
            for (int s = 0; s < S; s++)
                raw[s] = ui_rat[u * S + s] * ui_vot[u * S + s] * ui_tim[u * S + s];
        } else {
            const int v = V[Ep];
#pragma unroll
            for (int s = 0; s < S; s++)
                raw[s] = iu_rat[v * S + s] * iu_vot[v * S + s] * iu_tim[v * S + s];
        }
        float m = raw[0];
#pragma unroll
        for (int s = 1; s < S; s++) m = fmaxf(m, raw[s]);
        float wv[S], sum = 0.f;
#pragma unroll
        for (int s = 0; s < S; s++) { wv[s] = __expf(raw[s] - m); sum += wv[s]; }
        const float inv = __fdividef(1.0f, sum);
#pragma unroll
        for (int s = 0; s < S; s++) swt[pe][side][s] = wv[s] * inv;
    } else {
        const int base = (tid - 96) * 8;  // 160 threads x 8 = 1280 = 32 elems x 40 slots
#pragma unroll
        for (int j = 0; j < 8; j++) {
            const int i = base + j;
            const int pe = i / 40, slot = i - 40 * pe;
            int Ep = ebase + pe; if (Ep > batch - 1) Ep = batch - 1;
            if (slot < 32) {
                const int set = slot >> 3, s = slot & 7;
                int idx;
                if (set == 0)      idx = n_uu[U[Ep] * S + s];
                else if (set == 1) idx = n_ui[U[Ep] * S + s];
                else if (set == 2) idx = n_iu[V[Ep] * S + s];
                else               idx = n_ii[V[Ep] * S + s];
                snid[pe][set][s] = idx;
            } else {
                srid[pe][slot - 32] = n_ir[V[Ep] * S + (slot - 32)];
            }
        }
    }
    __syncthreads();  // #1

    // ================= phase 2: gathers + aggregation (8 threads/elem) ==========
    {
        const int e = tid >> 3, h = tid & 7;
        const int E = ebase + e;
        const int Ec = (E < batch) ? E : (batch - 1);
        const int u = U[Ec], v = V[Ec];

        const float4 ueA = uf4[u * 16 + 2 * h];
        const float4 ueB = uf4[u * 16 + 2 * h + 1];
        float4 xuA = ueA, xuB = ueB;
#pragma unroll
        for (int s = 0; s < S; s++) {
            const float w = swt[e][0][s]; const int id = snid[e][0][s];
            const float4 nA = uf4[id * 16 + 2 * h], nB = uf4[id * 16 + 2 * h + 1];
            xuA.x = fmaf(w, nA.x, xuA.x); xuA.y = fmaf(w, nA.y, xuA.y);
            xuA.z = fmaf(w, nA.z, xuA.z); xuA.w = fmaf(w, nA.w, xuA.w);
            xuB.x = fmaf(w, nB.x, xuB.x); xuB.y = fmaf(w, nB.y, xuB.y);
            xuB.z = fmaf(w, nB.z, xuB.z); xuB.w = fmaf(w, nB.w, xuB.w);
        }
#pragma unroll
        for (int s = 0; s < S; s++) {
            const float w = swt[e][1][s]; const int id = snid[e][1][s];
            const float4 nA = if4[id * 16 + 2 * h], nB = if4[id * 16 + 2 * h + 1];
            xuA.x = fmaf(w, nA.x, xuA.x); xuA.y = fmaf(w, nA.y, xuA.y);
            xuA.z = fmaf(w, nA.z, xuA.z); xuA.w = fmaf(w, nA.w, xuA.w);
            xuB.x = fmaf(w, nB.x, xuB.x); xuB.y = fmaf(w, nB.y, xuB.y);
            xuB.z = fmaf(w, nB.z, xuB.z); xuB.w = fmaf(w, nB.w, xuB.w);
        }
        float4 xvA = if4[v * 16 + 2 * h], xvB = if4[v * 16 + 2 * h + 1];
#pragma unroll
        for (int s = 0; s < S; s++) {
            const float w = swt[e][2][s]; const int id = snid[e][2][s];
            const float4 nA = uf4[id * 16 + 2 * h], nB = uf4[id * 16 + 2 * h + 1];
            xvA.x = fmaf(w, nA.x, xvA.x); xvA.y = fmaf(w, nA.y, xvA.y);
            xvA.z = fmaf(w, nA.z, xvA.z); xvA.w = fmaf(w, nA.w, xvA.w);
            xvB.x = fmaf(w, nB.x, xvB.x); xvB.y = fmaf(w, nB.y, xvB.y);
            xvB.z = fmaf(w, nB.z, xvB.z); xvB.w = fmaf(w, nB.w, xvB.w);
        }

        // KG attention
        float att[S];
#pragma unroll
        for (int s = 0; s < S; s++) {
            const int id = srid[e][s];
            const float4 rA = rf4[id * 16 + 2 * h], rB = rf4[id * 16 + 2 * h + 1];
            float p = ueA.x * rA.x;
            p = fmaf(ueA.y, rA.y, p); p = fmaf(ueA.z, rA.z, p); p = fmaf(ueA.w, rA.w, p);
            p = fmaf(ueB.x, rB.x, p); p = fmaf(ueB.y, rB.y, p);
            p = fmaf(ueB.z, rB.z, p); p = fmaf(ueB.w, rB.w, p);
            att[s] = p;
        }
#pragma unroll
        for (int s = 0; s < S; s++) att[s] = hsum8(att[s]);
        {
            float m = att[0];
#pragma unroll
            for (int s = 1; s < S; s++) m = fmaxf(m, att[s]);
            float wv[S], sum = 0.f;
#pragma unroll
            for (int s = 0; s < S; s++) { wv[s] = __expf(att[s] - m); sum += wv[s]; }
            const float inv = __fdividef(1.0f, sum);
#pragma unroll
            for (int s = 0; s < S; s++) {
                const float w = wv[s] * inv; const int id = snid[e][3][s];
                const float4 nA = if4[id * 16 + 2 * h], nB = if4[id * 16 + 2 * h + 1];
                xvA.x = fmaf(w, nA.x, xvA.x); xvA.y = fmaf(w, nA.y, xvA.y);
                xvA.z = fmaf(w, nA.z, xvA.z); xvA.w = fmaf(w, nA.w, xvA.w);
                xvB.x = fmaf(w, nB.x, xvB.x); xvB.y = fmaf(w, nB.y, xvB.y);
                xvB.z = fmaf(w, nB.z, xvB.z); xvB.w = fmaf(w, nB.w, xvB.w);
            }
        }

        // transpose-store with XOR swizzle: x[e][k] -> sxt[k*XP + (e ^ 4*(k>>3))]
        // this thread owns k = 8h..8h+7, so swizzle term is 4*h (conflict-free STS)
        const int c = e ^ (h << 2);
        const int b0 = (8 * h) * XP + c;
        sxtu[b0 + 0 * XP] = xuA.x; sxtu[b0 + 1 * XP] = xuA.y;
        sxtu[b0 + 2 * XP] = xuA.z; sxtu[b0 + 3 * XP] = xuA.w;
        sxtu[b0 + 4 * XP] = xuB.x; sxtu[b0 + 5 * XP] = xuB.y;
        sxtu[b0 + 6 * XP] = xuB.z; sxtu[b0 + 7 * XP] = xuB.w;
        sxtv[b0 + 0 * XP] = xvA.x; sxtv[b0 + 1 * XP] = xvA.y;
        sxtv[b0 + 2 * XP] = xvA.z; sxtv[b0 + 3 * XP] = xvA.w;
        sxtv[b0 + 4 * XP] = xvB.x; sxtv[b0 + 5 * XP] = xvB.y;
        sxtv[b0 + 6 * XP] = xvB.z; sxtv[b0 + 7 * XP] = xvB.w;
    }
    __syncthreads();  // #2

    // ================= phase 3: two matvec passes (packed f32x2 FMA) ============
    const int q  = tid >> 4;      // col group: cols 4q..4q+3
    const int ep = tid & 15;      // elem pair: elems 2ep, 2ep+1
    float4 hu0, hu1, hv0, hv1;

    // ---- pass U ----
    {
        const float4 b4 = ((const float4*)sbu)[q];
        unsigned long long a00 = pk2(b4.x, b4.y), a01 = pk2(b4.z, b4.w);
        unsigned long long a10 = a00, a11 = a01;
        for (int a = 0; a < 8; a++) {
            const int cswz = (2 * ep) ^ (a << 2);
#pragma unroll
            for (int j = 0; j < 8; j++) {
                const int k = a * 8 + j;
                const ulonglong2 w2 = *(const ulonglong2*)&sW[k * D + 4 * q];
                const float2 x2 = *(const float2*)&sxtu[k * XP + cswz];
                const unsigned long long d0 = pk2(x2.x, x2.x);
                const unsigned long long d1 = pk2(x2.y, x2.y);
                fma2(a00, d0, w2.x); fma2(a01, d0, w2.y);
                fma2(a10, d1, w2.x); fma2(a11, d1, w2.y);
            }
        }
        upk2(hu0.x, hu0.y, a00); upk2(hu0.z, hu0.w, a01);
        upk2(hu1.x, hu1.y, a10); upk2(hu1.z, hu1.w, a11);
    }
    __syncthreads();  // #3: everyone done reading sW(Wu) and sxtu

    // store hu into reused sxtu as [32][68]; reload sW with Wv
    {
        float* __restrict__ hu = sxtu;
        hu0.x = fmaxf(hu0.x, 0.f); hu0.y = fmaxf(hu0.y, 0.f);
        hu0.z = fmaxf(hu0.z, 0.f); hu0.w = fmaxf(hu0.w, 0.f);
        hu1.x = fmaxf(hu1.x, 0.f); hu1.y = fmaxf(hu1.y, 0.f);
        hu1.z = fmaxf(hu1.z, 0.f); hu1.w = fmaxf(hu1.w, 0.f);
        *(float4*)&hu[(2 * ep) * 68 + 4 * q]     = hu0;
        *(float4*)&hu[(2 * ep + 1) * 68 + 4 * q] = hu1;
    }
#pragma unroll
    for (int i = tid; i < D * D / 4; i += NT)
        ((float4*)sW)[i] = ((const float4*)Wv)[i];
    __syncthreads();  // #4

    // ---- pass V ----
    {
        const float4 b4 = ((const float4*)sbv)[q];
        unsigned long long a00 = pk2(b4.x, b4.y), a01 = pk2(b4.z, b4.w);
        unsigned long long a10 = a00, a11 = a01;
        for (int a = 0; a < 8; a++) {
            const int cswz = (2 * ep) ^ (a << 2);
#pragma unroll
            for (int j = 0; j < 8; j++) {
                const int k = a * 8 + j;
                const ulonglong2 w2 = *(const ulonglong2*)&sW[k * D + 4 * q];
                const float2 x2 = *(const float2*)&sxtv[k * XP + cswz];
                const unsigned long long d0 = pk2(x2.x, x2.x);
                const unsigned long long d1 = pk2(x2.y, x2.y);
                fma2(a00, d0, w2.x); fma2(a01, d0, w2.y);
                fma2(a10, d1, w2.x); fma2(a11, d1, w2.y);
            }
        }
        upk2(hv0.x, hv0.y, a00); upk2(hv0.z, hv0.w, a01);
        upk2(hv1.x, hv1.y, a10); upk2(hv1.z, hv1.w, a11);
    }
    __syncthreads();  // #5: everyone done reading sxtv

    {
        float* __restrict__ hv = sxtv;
        hv0.x = fmaxf(hv0.x, 0.f); hv0.y = fmaxf(hv0.y, 0.f);
        hv0.z = fmaxf(hv0.z, 0.f); hv0.w = fmaxf(hv0.w, 0.f);
        hv1.x = fmaxf(hv1.x, 0.f); hv1.y = fmaxf(hv1.y, 0.f);
        hv1.z = fmaxf(hv1.z, 0.f); hv1.w = fmaxf(hv1.w, 0.f);
        *(float4*)&hv[(2 * ep) * 68 + 4 * q]     = hv0;
        *(float4*)&hv[(2 * ep + 1) * 68 + 4 * q] = hv1;
    }
    __syncthreads();  // #6

    // ================= final dot + sigmoid ======================================
    {
        const int e = tid >> 3, oct = tid & 7;
        const float* __restrict__ hu = sxtu;
        const float* __restrict__ hv = sxtv;
        const float4 ua = ((const float4*)hu)[e * 17 + 2 * oct];
        const float4 ub = ((const float4*)hu)[e * 17 + 2 * oct + 1];
        const float4 va = ((const float4*)hv)[e * 17 + 2 * oct];
        const float4 vb = ((const float4*)hv)[e * 17 + 2 * oct + 1];
        float p = ua.x * va.x;
        p = fmaf(ua.y, va.y, p); p = fmaf(ua.z, va.z, p); p = fmaf(ua.w, va.w, p);
        p = fmaf(ub.x, vb.x, p); p = fmaf(ub.y, vb.y, p);
        p = fmaf(ub.z, vb.z, p); p = fmaf(ub.w, vb.w, p);
        p = hsum8(p);
        const int E = ebase + e;
        if (oct == 0 && E < batch)
            out[E] = __fdividef(5.0f, 1.0f + __expf(-p));
    }
}

extern "C" void kernel_launch(void* const* d_in, const int* in_sizes, int n_in,
                              void* d_out, int out_size) {
    const int*   U        = (const int*)  d_in[0];
    const int*   V        = (const int*)  d_in[1];
    const float* usr_feat = (const float*)d_in[2];
    const float* item_feat= (const float*)d_in[3];
    const float* rel_feat = (const float*)d_in[4];
    const int*   n_uu     = (const int*)  d_in[5];
    const float* uu_st    = (const float*)d_in[6];
    const int*   n_ui     = (const int*)  d_in[7];
    const float* ui_rat   = (const float*)d_in[8];
    const float* ui_vot   = (const float*)d_in[9];
    const float* ui_tim   = (const float*)d_in[10];
    const int*   n_iu     = (const int*)  d_in[11];
    const float* iu_rat   = (const float*)d_in[12];
    const float* iu_vot   = (const float*)d_in[13];
    const float* iu_tim   = (const float*)d_in[14];
    const int*   n_ii     = (const int*)  d_in[15];
    const int*   n_ir     = (const int*)  d_in[16];
    const float* Wu       = (const float*)d_in[17];
    const float* bu       = (const float*)d_in[18];
    const float* Wv       = (const float*)d_in[19];
    const float* bv       = (const float*)d_in[20];
    float* out = (float*)d_out;

    const int batch = in_sizes[0];
    const int nblocks = (batch + EPB - 1) / EPB;

    sestkgcn_kernel<<<nblocks, NT>>>(
        U, V, usr_feat, item_feat, rel_feat,
        n_uu, uu_st, n_ui, ui_rat, ui_vot, ui_tim,
        n_iu, iu_rat, iu_vot, iu_tim, n_ii, n_ir,
        Wu, bu, Wv, bv, out, batch);
}